// round 1
// baseline (speedup 1.0000x reference)
#include <cuda_runtime.h>
#include <math.h>

#define Bb 8
#define Cc 384
#define Nn 1024
#define HEADS 8
#define KD 32
#define VD 128
#define QKV_C 1536
#define FC1_C 768
#define EPS 1e-5f

// ---------------- scratch (static device globals; no allocation) ----------------
__device__ float g_y[(long)Bb*QKV_C*Nn];        // qkv pre/post-norm   (50 MB)
__device__ float g_att[(long)Bb*HEADS*Nn*Nn];   // attention matrix    (268 MB)
__device__ float g_o2[(long)Bb*HEADS*VD*Nn];    // gelu(attn out)      (33 MB)
__device__ float g_x2[(long)Bb*Cc*Nn];          // x + merge branch
__device__ float g_h1[(long)Bb*FC1_C*Nn];       // gelu(fc1 norm)
__device__ float g_tmp[(long)Bb*FC1_C*Nn];      // gemm outputs pre-norm
__device__ float g_mean[QKV_C];
__device__ float g_rstd[QKV_C];

__device__ __forceinline__ float warpSum(float v){
    #pragma unroll
    for (int o=16;o;o>>=1) v += __shfl_xor_sync(0xffffffffu, v, o);
    return v;
}
__device__ __forceinline__ float warpMax(float v){
    #pragma unroll
    for (int o=16;o;o>>=1) v = fmaxf(v, __shfl_xor_sync(0xffffffffu, v, o));
    return v;
}
__device__ __forceinline__ float gelu_exact(float x){
    return 0.5f * x * (1.0f + erff(x * 0.7071067811865476f));
}

// ---------------- NN SGEMM: C[M,N] = A[M,K] * B[K,N], A shared (weights), B/C batched over z
__global__ __launch_bounds__(256) void sgemm_nn(
    const float* __restrict__ A, const float* __restrict__ B, float* __restrict__ C,
    int M, int N, int K, long strideB, long strideC)
{
    __shared__ float As[16][64];
    __shared__ float Bs[16][64];
    const float* Bz = B + (long)blockIdx.z * strideB;
    float* Cz = C + (long)blockIdx.z * strideC;
    const int bm = blockIdx.y * 64, bn = blockIdx.x * 64;
    const int tid = threadIdx.x;
    const int tx = tid & 15, ty = tid >> 4;
    float acc[4][4] = {};
    const int ra = tid >> 2, ka = (tid & 3) * 4;   // A tile loader: row, k-quad
    const int kb = tid >> 4, nb = (tid & 15) * 4;  // B tile loader: k-row, n-quad
    for (int k0 = 0; k0 < K; k0 += 16) {
        float4 a4 = *reinterpret_cast<const float4*>(&A[(long)(bm + ra) * K + k0 + ka]);
        As[ka+0][ra] = a4.x; As[ka+1][ra] = a4.y; As[ka+2][ra] = a4.z; As[ka+3][ra] = a4.w;
        float4 b4 = *reinterpret_cast<const float4*>(&Bz[(long)(k0 + kb) * N + bn + nb]);
        *reinterpret_cast<float4*>(&Bs[kb][nb]) = b4;
        __syncthreads();
        #pragma unroll
        for (int k = 0; k < 16; k++) {
            float av[4], bv[4];
            #pragma unroll
            for (int i = 0; i < 4; i++) av[i] = As[k][ty*4+i];
            #pragma unroll
            for (int j = 0; j < 4; j++) bv[j] = Bs[k][tx*4+j];
            #pragma unroll
            for (int i = 0; i < 4; i++)
                #pragma unroll
                for (int j = 0; j < 4; j++) acc[i][j] += av[i]*bv[j];
        }
        __syncthreads();
    }
    #pragma unroll
    for (int i = 0; i < 4; i++)
        #pragma unroll
        for (int j = 0; j < 4; j++)
            Cz[(long)(bm + ty*4+i) * N + bn + tx*4+j] = acc[i][j];
}

// ---------------- att = scale * q^T k (TN, K=32 fully resident) ----------------
__global__ __launch_bounds__(256) void att_qk(const float* __restrict__ y, float* __restrict__ att, float scale)
{
    const int z = blockIdx.z, b = z >> 3, h = z & 7;
    const float* Q = y + ((long)b * QKV_C + h * (2*KD + VD)) * Nn;
    const float* Kp = Q + KD * Nn;
    float* Cz = att + (long)z * Nn * Nn;
    __shared__ float Qs[32][64];
    __shared__ float Ks[32][64];
    const int bm = blockIdx.y * 64, bn = blockIdx.x * 64;
    const int tid = threadIdx.x;
    const int tx = tid & 15, ty = tid >> 4;
    // load 32x64 tiles (2048 elems, 8 per thread), coalesced along n
    for (int l = tid; l < 2048; l += 256) {
        int k = l >> 6, m = l & 63;
        Qs[k][m] = Q[(long)k * Nn + bm + m];
        Ks[k][m] = Kp[(long)k * Nn + bn + m];
    }
    __syncthreads();
    float acc[4][4] = {};
    #pragma unroll
    for (int k = 0; k < 32; k++) {
        float av[4], bv[4];
        #pragma unroll
        for (int i = 0; i < 4; i++) av[i] = Qs[k][ty*4+i];
        #pragma unroll
        for (int j = 0; j < 4; j++) bv[j] = Ks[k][tx*4+j];
        #pragma unroll
        for (int i = 0; i < 4; i++)
            #pragma unroll
            for (int j = 0; j < 4; j++) acc[i][j] += av[i]*bv[j];
    }
    #pragma unroll
    for (int i = 0; i < 4; i++)
        #pragma unroll
        for (int j = 0; j < 4; j++)
            Cz[(long)(bm + ty*4+i) * Nn + bn + tx*4+j] = acc[i][j] * scale;
}

// ---------------- row softmax over 1024 (one block of 128 per row) ----------------
__global__ __launch_bounds__(128) void softmax_rows(float* __restrict__ att)
{
    float* p = att + (long)blockIdx.x * Nn;
    const int t = threadIdx.x;
    float vals[8];
    float mx = -INFINITY;
    #pragma unroll
    for (int i = 0; i < 8; i++) { vals[i] = p[t + 128*i]; mx = fmaxf(mx, vals[i]); }
    __shared__ float sh[4];
    mx = warpMax(mx);
    if ((t & 31) == 0) sh[t >> 5] = mx;
    __syncthreads();
    mx = fmaxf(fmaxf(sh[0], sh[1]), fmaxf(sh[2], sh[3]));
    float s = 0.f;
    #pragma unroll
    for (int i = 0; i < 8; i++) { vals[i] = __expf(vals[i] - mx); s += vals[i]; }
    s = warpSum(s);
    if ((t & 31) == 0) sh[t >> 5] = s;
    __syncthreads();
    s = sh[0] + sh[1] + sh[2] + sh[3];
    float inv = 1.0f / s;
    #pragma unroll
    for (int i = 0; i < 8; i++) p[t + 128*i] = vals[i] * inv;
}

// ---------------- o2 = gelu( V @ Att^T )  (NT), per (b,h) ----------------
__global__ __launch_bounds__(256) void att_ov(const float* __restrict__ y, const float* __restrict__ att,
                                              float* __restrict__ o2)
{
    const int z = blockIdx.z, b = z >> 3, h = z & 7;
    const float* V  = y + ((long)b * QKV_C + h * (2*KD + VD) + 2*KD) * Nn;  // [128, 1024]
    const float* Az = att + (long)z * Nn * Nn;                               // [1024, 1024] row-major (n,m)
    float* Cz = o2 + ((long)b * (HEADS*VD) + h * VD) * Nn;                   // [128, 1024]
    __shared__ float Vs[16][64];
    __shared__ float Ts[16][64];
    const int bm = blockIdx.y * 64, bn = blockIdx.x * 64;
    const int tid = threadIdx.x;
    const int tx = tid & 15, ty = tid >> 4;
    const int r = tid >> 2, kk = (tid & 3) * 4;
    float acc[4][4] = {};
    for (int k0 = 0; k0 < Nn; k0 += 16) {
        float4 v4 = *reinterpret_cast<const float4*>(&V[(long)(bm + r) * Nn + k0 + kk]);
        Vs[kk+0][r] = v4.x; Vs[kk+1][r] = v4.y; Vs[kk+2][r] = v4.z; Vs[kk+3][r] = v4.w;
        float4 t4 = *reinterpret_cast<const float4*>(&Az[(long)(bn + r) * Nn + k0 + kk]);
        Ts[kk+0][r] = t4.x; Ts[kk+1][r] = t4.y; Ts[kk+2][r] = t4.z; Ts[kk+3][r] = t4.w;
        __syncthreads();
        #pragma unroll
        for (int k = 0; k < 16; k++) {
            float av[4], bv[4];
            #pragma unroll
            for (int i = 0; i < 4; i++) av[i] = Vs[k][ty*4+i];
            #pragma unroll
            for (int j = 0; j < 4; j++) bv[j] = Ts[k][tx*4+j];
            #pragma unroll
            for (int i = 0; i < 4; i++)
                #pragma unroll
                for (int j = 0; j < 4; j++) acc[i][j] += av[i]*bv[j];
        }
        __syncthreads();
    }
    #pragma unroll
    for (int i = 0; i < 4; i++)
        #pragma unroll
        for (int j = 0; j < 4; j++)
            Cz[(long)(bm + ty*4+i) * Nn + bn + tx*4+j] = gelu_exact(acc[i][j]);
}

// ---------------- BN stats: one block per channel, reduce over B*N = 8192 ----------------
__global__ __launch_bounds__(256) void bn_stats(const float* __restrict__ y, float* __restrict__ mean,
                                                float* __restrict__ rstd, int C)
{
    const int c = blockIdx.x;
    float s = 0.f, s2 = 0.f;
    for (int i = threadIdx.x; i < Bb * Nn; i += 256) {
        int b = i >> 10, n = i & 1023;
        float v = y[((long)b * C + c) * Nn + n];
        s += v; s2 += v * v;
    }
    __shared__ float ss[8], ss2[8];
    s = warpSum(s); s2 = warpSum(s2);
    int w = threadIdx.x >> 5;
    if ((threadIdx.x & 31) == 0) { ss[w] = s; ss2[w] = s2; }
    __syncthreads();
    if (threadIdx.x == 0) {
        float ts = 0.f, ts2 = 0.f;
        #pragma unroll
        for (int i = 0; i < 8; i++) { ts += ss[i]; ts2 += ss2[i]; }
        float m = ts / (float)(Bb * Nn);
        float var = ts2 / (float)(Bb * Nn) - m * m;
        mean[c] = m;
        rstd[c] = rsqrtf(var + EPS);
    }
}

// ---------------- BN apply variants ----------------
__global__ __launch_bounds__(256) void bn_apply_inplace(float* __restrict__ y,
    const float* __restrict__ mean, const float* __restrict__ rstd,
    const float* __restrict__ gg, const float* __restrict__ bb, int C, long total)
{
    long stride = (long)gridDim.x * blockDim.x;
    for (long i = (long)blockIdx.x * blockDim.x + threadIdx.x; i < total; i += stride) {
        int c = (int)((i >> 10) % C);
        y[i] = (y[i] - mean[c]) * rstd[c] * gg[c] + bb[c];
    }
}

__global__ __launch_bounds__(256) void bn_apply_residual(const float* __restrict__ src, const float* __restrict__ res,
    float* __restrict__ dst, const float* __restrict__ mean, const float* __restrict__ rstd,
    const float* __restrict__ gg, const float* __restrict__ bb, int C, long total)
{
    long stride = (long)gridDim.x * blockDim.x;
    for (long i = (long)blockIdx.x * blockDim.x + threadIdx.x; i < total; i += stride) {
        int c = (int)((i >> 10) % C);
        dst[i] = res[i] + (src[i] - mean[c]) * rstd[c] * gg[c] + bb[c];
    }
}

__global__ __launch_bounds__(256) void bn_apply_gelu(const float* __restrict__ src, float* __restrict__ dst,
    const float* __restrict__ mean, const float* __restrict__ rstd,
    const float* __restrict__ gg, const float* __restrict__ bb, int C, long total)
{
    long stride = (long)gridDim.x * blockDim.x;
    for (long i = (long)blockIdx.x * blockDim.x + threadIdx.x; i < total; i += stride) {
        int c = (int)((i >> 10) % C);
        float v = (src[i] - mean[c]) * rstd[c] * gg[c] + bb[c];
        dst[i] = gelu_exact(v);
    }
}

// ---------------- launch ----------------
extern "C" void kernel_launch(void* const* d_in, const int* in_sizes, int n_in,
                              void* d_out, int out_size)
{
    const float* x       = (const float*)d_in[0];
    const float* w_qkv   = (const float*)d_in[1];
    const float* gqkv    = (const float*)d_in[2];
    const float* bqkv    = (const float*)d_in[3];
    const float* w_merge = (const float*)d_in[4];
    const float* gmerge  = (const float*)d_in[5];
    const float* bmerge  = (const float*)d_in[6];
    const float* w_fc1   = (const float*)d_in[7];
    const float* gfc1    = (const float*)d_in[8];
    const float* bfc1    = (const float*)d_in[9];
    const float* w_fc2   = (const float*)d_in[10];
    const float* gfc2    = (const float*)d_in[11];
    const float* bfc2    = (const float*)d_in[12];
    float* out = (float*)d_out;

    float *yb, *attb, *o2b, *x2b, *h1b, *tmpb, *meanb, *rstdb;
    cudaGetSymbolAddress((void**)&yb,    g_y);
    cudaGetSymbolAddress((void**)&attb,  g_att);
    cudaGetSymbolAddress((void**)&o2b,   g_o2);
    cudaGetSymbolAddress((void**)&x2b,   g_x2);
    cudaGetSymbolAddress((void**)&h1b,   g_h1);
    cudaGetSymbolAddress((void**)&tmpb,  g_tmp);
    cudaGetSymbolAddress((void**)&meanb, g_mean);
    cudaGetSymbolAddress((void**)&rstdb, g_rstd);

    const float scale = 0.17677669529663687f; // 32^-0.5

    // 1) qkv conv1x1: g_y[b,1536,1024] = w_qkv(1536x384) @ x_b(384x1024)
    sgemm_nn<<<dim3(Nn/64, QKV_C/64, Bb), 256>>>(w_qkv, x, yb, QKV_C, Nn, Cc,
                                                 (long)Cc*Nn, (long)QKV_C*Nn);
    // 2) BN(qkv)
    bn_stats<<<QKV_C, 256>>>(yb, meanb, rstdb, QKV_C);
    bn_apply_inplace<<<4096, 256>>>(yb, meanb, rstdb, gqkv, bqkv, QKV_C, (long)Bb*QKV_C*Nn);
    // 3) att = softmax(scale * q^T k)
    att_qk<<<dim3(Nn/64, Nn/64, Bb*HEADS), 256>>>(yb, attb, scale);
    softmax_rows<<<Bb*HEADS*Nn, 128>>>(attb);
    // 4) o2 = gelu(V @ att^T)
    att_ov<<<dim3(Nn/64, VD/64, Bb*HEADS), 256>>>(yb, attb, o2b);
    // 5) merge conv + BN + residual -> x2
    sgemm_nn<<<dim3(Nn/64, Cc/64, Bb), 256>>>(w_merge, o2b, tmpb, Cc, Nn, HEADS*VD,
                                              (long)HEADS*VD*Nn, (long)Cc*Nn);
    bn_stats<<<Cc, 256>>>(tmpb, meanb, rstdb, Cc);
    bn_apply_residual<<<2048, 256>>>(tmpb, x, x2b, meanb, rstdb, gmerge, bmerge, Cc, (long)Bb*Cc*Nn);
    // 6) fc1 + BN + gelu -> h1
    sgemm_nn<<<dim3(Nn/64, FC1_C/64, Bb), 256>>>(w_fc1, x2b, tmpb, FC1_C, Nn, Cc,
                                                 (long)Cc*Nn, (long)FC1_C*Nn);
    bn_stats<<<FC1_C, 256>>>(tmpb, meanb, rstdb, FC1_C);
    bn_apply_gelu<<<3072, 256>>>(tmpb, h1b, meanb, rstdb, gfc1, bfc1, FC1_C, (long)Bb*FC1_C*Nn);
    // 7) fc2 + BN + residual -> out
    sgemm_nn<<<dim3(Nn/64, Cc/64, Bb), 256>>>(w_fc2, h1b, tmpb, Cc, Nn, FC1_C,
                                              (long)FC1_C*Nn, (long)Cc*Nn);
    bn_stats<<<Cc, 256>>>(tmpb, meanb, rstdb, Cc);
    bn_apply_residual<<<2048, 256>>>(tmpb, x2b, out, meanb, rstdb, gfc2, bfc2, Cc, (long)Bb*Cc*Nn);
}

// round 2
// speedup vs baseline: 2.4419x; 2.4419x over previous
#include <cuda_runtime.h>
#include <math.h>
#include <stdint.h>

#define Bb 8
#define Cc 384
#define Nn 1024
#define HEADS 8
#define KD 32
#define VD 128
#define QKV_C 1536
#define FC1_C 768
#define EPS 1e-5f

// ---------------- scratch (static device globals; no allocation) ----------------
__device__ float g_y[(long)Bb*QKV_C*Nn];        // qkv pre/post-norm   (50 MB)
__device__ float g_att[(long)Bb*HEADS*Nn*Nn];   // attention matrix    (268 MB)
__device__ float g_o2[(long)Bb*HEADS*VD*Nn];    // gelu(attn out)      (33 MB)
__device__ float g_x2[(long)Bb*Cc*Nn];          // x + merge branch
__device__ float g_h1[(long)Bb*FC1_C*Nn];       // gelu(fc1 norm)
__device__ float g_tmp[(long)Bb*FC1_C*Nn];      // gemm outputs pre-norm
__device__ float g_mean[QKV_C];
__device__ float g_rstd[QKV_C];

__device__ __forceinline__ float warpSum(float v){
    #pragma unroll
    for (int o=16;o;o>>=1) v += __shfl_xor_sync(0xffffffffu, v, o);
    return v;
}
__device__ __forceinline__ float warpMax(float v){
    #pragma unroll
    for (int o=16;o;o>>=1) v = fmaxf(v, __shfl_xor_sync(0xffffffffu, v, o));
    return v;
}
__device__ __forceinline__ float gelu_exact(float x){
    return 0.5f * x * (1.0f + erff(x * 0.7071067811865476f));
}
// round fp32 -> tf32 (RNA) so mma truncation bias is removed
__device__ __forceinline__ float to_tf32(float x){
    uint32_t u;
    asm("cvt.rna.tf32.f32 %0, %1;" : "=r"(u) : "f"(x));
    return __uint_as_float(u);
}
__device__ __forceinline__ void mma_tf32(float c[4],
    uint32_t a0, uint32_t a1, uint32_t a2, uint32_t a3, uint32_t b0, uint32_t b1)
{
    asm volatile("mma.sync.aligned.m16n8k8.row.col.f32.tf32.tf32.f32 "
        "{%0,%1,%2,%3}, {%4,%5,%6,%7}, {%8,%9}, {%0,%1,%2,%3};"
        : "+f"(c[0]), "+f"(c[1]), "+f"(c[2]), "+f"(c[3])
        : "r"(a0), "r"(a1), "r"(a2), "r"(a3), "r"(b0), "r"(b1));
}

// =====================================================================
// Unified tf32 tensor-core GEMM.  C[M,N] = op(A) * op(B), batched over z.
// BM=BN=128, BK=16. 256 threads = 8 warps (4 in M x 2 in N), warp tile 32x64.
// AMODE 0: A global row-major [M,K] (lda=K-ish)  -> transpose-store to As[k][m]
// AMODE 1: A global k-major   [K,ldm]            -> direct store
// BMODE 0: B global k-major   [K,N]              -> direct store to Bs[k][n]
// BMODE 1: B global row-major [N,K]              -> transpose-store
// ZMODE 0: linear strides (weights shared);  1: q^T k head addressing;
// ZMODE 2: V @ att^T head addressing
// EPI   0: plain; 1: *alpha; 2: gelu
// =====================================================================
#define SMS 136   // smem row stride (floats): 136%32==8 -> frag loads conflict-free

template<int AMODE,int BMODE,int ZMODE,int EPI>
__global__ __launch_bounds__(256,2) void mm_tf32(
    const float* __restrict__ A, const float* __restrict__ B, float* __restrict__ C,
    int M, int N, int K, int lda, int ldb,
    long strideB, long strideC, float alpha)
{
    __shared__ __align__(16) float As[2][16][SMS];
    __shared__ __align__(16) float Bs[2][16][SMS];

    const int z = blockIdx.z;
    long aOff, bOff, cOff;
    if (ZMODE == 0) {
        aOff = 0; bOff = (long)z * strideB; cOff = (long)z * strideC;
    } else {
        long base = (long)(z >> 3) * QKV_C * Nn + (long)(z & 7) * (2*KD + VD) * Nn;
        if (ZMODE == 1) { aOff = base;                 bOff = base + (long)KD * Nn;  cOff = (long)z * Nn * Nn; }
        else            { aOff = base + (long)2*KD*Nn; bOff = (long)z * Nn * Nn;
                          cOff = ((long)(z >> 3) * HEADS * VD + (long)(z & 7) * VD) * Nn; }
    }
    const float* Ab = A + aOff;
    const float* Bc = B + bOff;
    float* Cz = C + cOff;

    const int bm = blockIdx.y * 128, bn = blockIdx.x * 128;
    const int tid = threadIdx.x;
    const int w = tid >> 5, l = tid & 31;
    const int wm = (w >> 1) * 32, wn = (w & 1) * 64;
    const int r = l >> 2, qc = l & 3;

    float acc[2][8][4];
    #pragma unroll
    for (int i = 0; i < 2; i++)
        #pragma unroll
        for (int j = 0; j < 8; j++)
            #pragma unroll
            for (int k = 0; k < 4; k++) acc[i][j][k] = 0.f;

    float4 ra[2], rb[2];

    auto gload = [&](int k0){
        #pragma unroll
        for (int j = 0; j < 2; j++){
            int i = tid + j*256;
            if (AMODE == 0) { int row = i >> 2, kq = (i & 3) * 4;
                ra[j] = *reinterpret_cast<const float4*>(&Ab[(long)(bm+row)*lda + k0+kq]); }
            else            { int kk = i >> 5, mq = (i & 31) * 4;
                ra[j] = *reinterpret_cast<const float4*>(&Ab[(long)(k0+kk)*lda + bm+mq]); }
        }
        #pragma unroll
        for (int j = 0; j < 2; j++){
            int i = tid + j*256;
            if (BMODE == 0) { int kk = i >> 5, nq = (i & 31) * 4;
                rb[j] = *reinterpret_cast<const float4*>(&Bc[(long)(k0+kk)*ldb + bn+nq]); }
            else            { int row = i >> 2, kq = (i & 3) * 4;
                rb[j] = *reinterpret_cast<const float4*>(&Bc[(long)(bn+row)*ldb + k0+kq]); }
        }
    };

    auto sstore = [&](int buf){
        #pragma unroll
        for (int j = 0; j < 2; j++){
            int i = tid + j*256;
            if (AMODE == 0) { int row = i >> 2, kq = (i & 3) * 4;
                As[buf][kq+0][row] = to_tf32(ra[j].x);
                As[buf][kq+1][row] = to_tf32(ra[j].y);
                As[buf][kq+2][row] = to_tf32(ra[j].z);
                As[buf][kq+3][row] = to_tf32(ra[j].w); }
            else            { int kk = i >> 5, mq = (i & 31) * 4;
                As[buf][kk][mq+0] = to_tf32(ra[j].x);
                As[buf][kk][mq+1] = to_tf32(ra[j].y);
                As[buf][kk][mq+2] = to_tf32(ra[j].z);
                As[buf][kk][mq+3] = to_tf32(ra[j].w); }
        }
        #pragma unroll
        for (int j = 0; j < 2; j++){
            int i = tid + j*256;
            if (BMODE == 0) { int kk = i >> 5, nq = (i & 31) * 4;
                Bs[buf][kk][nq+0] = to_tf32(rb[j].x);
                Bs[buf][kk][nq+1] = to_tf32(rb[j].y);
                Bs[buf][kk][nq+2] = to_tf32(rb[j].z);
                Bs[buf][kk][nq+3] = to_tf32(rb[j].w); }
            else            { int row = i >> 2, kq = (i & 3) * 4;
                Bs[buf][kq+0][row] = to_tf32(rb[j].x);
                Bs[buf][kq+1][row] = to_tf32(rb[j].y);
                Bs[buf][kq+2][row] = to_tf32(rb[j].z);
                Bs[buf][kq+3][row] = to_tf32(rb[j].w); }
        }
    };

    auto compute = [&](int buf){
        #pragma unroll
        for (int ks = 0; ks < 16; ks += 8){
            uint32_t af[2][4], bf[8][2];
            #pragma unroll
            for (int im = 0; im < 2; im++){
                af[im][0] = __float_as_uint(As[buf][ks+qc  ][wm+im*16+r  ]);
                af[im][1] = __float_as_uint(As[buf][ks+qc  ][wm+im*16+r+8]);
                af[im][2] = __float_as_uint(As[buf][ks+qc+4][wm+im*16+r  ]);
                af[im][3] = __float_as_uint(As[buf][ks+qc+4][wm+im*16+r+8]);
            }
            #pragma unroll
            for (int jn = 0; jn < 8; jn++){
                bf[jn][0] = __float_as_uint(Bs[buf][ks+qc  ][wn+jn*8+r]);
                bf[jn][1] = __float_as_uint(Bs[buf][ks+qc+4][wn+jn*8+r]);
            }
            #pragma unroll
            for (int im = 0; im < 2; im++)
                #pragma unroll
                for (int jn = 0; jn < 8; jn++)
                    mma_tf32(acc[im][jn], af[im][0], af[im][1], af[im][2], af[im][3],
                             bf[jn][0], bf[jn][1]);
        }
    };

    gload(0); sstore(0); __syncthreads();
    int buf = 0;
    for (int k0 = 0; k0 < K; k0 += 16){
        bool more = (k0 + 16) < K;
        if (more) gload(k0 + 16);
        compute(buf);
        if (more) { sstore(buf ^ 1); buf ^= 1; }
        __syncthreads();
    }

    #pragma unroll
    for (int im = 0; im < 2; im++){
        #pragma unroll
        for (int jn = 0; jn < 8; jn++){
            float v0 = acc[im][jn][0], v1 = acc[im][jn][1];
            float v2 = acc[im][jn][2], v3 = acc[im][jn][3];
            if (EPI == 1) { v0 *= alpha; v1 *= alpha; v2 *= alpha; v3 *= alpha; }
            if (EPI == 2) { v0 = gelu_exact(v0); v1 = gelu_exact(v1);
                            v2 = gelu_exact(v2); v3 = gelu_exact(v3); }
            int row = bm + wm + im*16 + r;
            int col = bn + wn + jn*8 + 2*qc;
            *reinterpret_cast<float2*>(&Cz[(long)row * N + col])     = make_float2(v0, v1);
            *reinterpret_cast<float2*>(&Cz[(long)(row+8) * N + col]) = make_float2(v2, v3);
        }
    }
}

// ---------------- row softmax over 1024 (one block of 256 per row, float4) -------
__global__ __launch_bounds__(256) void softmax_rows(float* __restrict__ att)
{
    float4* p = reinterpret_cast<float4*>(att + (long)blockIdx.x * Nn);
    const int t = threadIdx.x;
    float4 v = p[t];
    __shared__ float sh[8];
    float mx = fmaxf(fmaxf(v.x, v.y), fmaxf(v.z, v.w));
    mx = warpMax(mx);
    if ((t & 31) == 0) sh[t >> 5] = mx;
    __syncthreads();
    mx = sh[0];
    #pragma unroll
    for (int i = 1; i < 8; i++) mx = fmaxf(mx, sh[i]);
    v.x = __expf(v.x - mx); v.y = __expf(v.y - mx);
    v.z = __expf(v.z - mx); v.w = __expf(v.w - mx);
    float s = v.x + v.y + v.z + v.w;
    s = warpSum(s);
    __syncthreads();
    if ((t & 31) == 0) sh[t >> 5] = s;
    __syncthreads();
    s = sh[0] + sh[1] + sh[2] + sh[3] + sh[4] + sh[5] + sh[6] + sh[7];
    float inv = 1.0f / s;
    v.x *= inv; v.y *= inv; v.z *= inv; v.w *= inv;
    p[t] = v;
}

// ---------------- BN stats: one block per channel, reduce over B*N = 8192 --------
__global__ __launch_bounds__(256) void bn_stats(const float* __restrict__ y, float* __restrict__ mean,
                                                float* __restrict__ rstd, int C)
{
    const int c = blockIdx.x;
    float s = 0.f, s2 = 0.f;
    for (int i = threadIdx.x; i < Bb * Nn / 4; i += 256) {
        int b = i >> 8, n4 = i & 255;
        float4 v = *reinterpret_cast<const float4*>(&y[((long)b * C + c) * Nn + n4 * 4]);
        s  += v.x + v.y + v.z + v.w;
        s2 += v.x*v.x + v.y*v.y + v.z*v.z + v.w*v.w;
    }
    __shared__ float ss[8], ss2[8];
    s = warpSum(s); s2 = warpSum(s2);
    int w = threadIdx.x >> 5;
    if ((threadIdx.x & 31) == 0) { ss[w] = s; ss2[w] = s2; }
    __syncthreads();
    if (threadIdx.x == 0) {
        float ts = 0.f, ts2 = 0.f;
        #pragma unroll
        for (int i = 0; i < 8; i++) { ts += ss[i]; ts2 += ss2[i]; }
        float m = ts / (float)(Bb * Nn);
        float var = ts2 / (float)(Bb * Nn) - m * m;
        mean[c] = m;
        rstd[c] = rsqrtf(var + EPS);
    }
}

// ---------------- BN apply variants (float4) ----------------
__global__ __launch_bounds__(256) void bn_apply_inplace(float* __restrict__ y,
    const float* __restrict__ mean, const float* __restrict__ rstd,
    const float* __restrict__ gg, const float* __restrict__ bb, int C, long total4)
{
    float4* p = reinterpret_cast<float4*>(y);
    long stride = (long)gridDim.x * blockDim.x;
    for (long i = (long)blockIdx.x * blockDim.x + threadIdx.x; i < total4; i += stride) {
        int c = (int)((i >> 8) % C);
        float sc = rstd[c] * gg[c];
        float sh = bb[c] - mean[c] * sc;
        float4 v = p[i];
        v.x = v.x * sc + sh; v.y = v.y * sc + sh; v.z = v.z * sc + sh; v.w = v.w * sc + sh;
        p[i] = v;
    }
}

__global__ __launch_bounds__(256) void bn_apply_residual(const float* __restrict__ src, const float* __restrict__ res,
    float* __restrict__ dst, const float* __restrict__ mean, const float* __restrict__ rstd,
    const float* __restrict__ gg, const float* __restrict__ bb, int C, long total4)
{
    const float4* s4 = reinterpret_cast<const float4*>(src);
    const float4* r4 = reinterpret_cast<const float4*>(res);
    float4* d4 = reinterpret_cast<float4*>(dst);
    long stride = (long)gridDim.x * blockDim.x;
    for (long i = (long)blockIdx.x * blockDim.x + threadIdx.x; i < total4; i += stride) {
        int c = (int)((i >> 8) % C);
        float sc = rstd[c] * gg[c];
        float shf = bb[c] - mean[c] * sc;
        float4 v = s4[i]; float4 rr = r4[i];
        v.x = rr.x + v.x * sc + shf; v.y = rr.y + v.y * sc + shf;
        v.z = rr.z + v.z * sc + shf; v.w = rr.w + v.w * sc + shf;
        d4[i] = v;
    }
}

__global__ __launch_bounds__(256) void bn_apply_gelu(const float* __restrict__ src, float* __restrict__ dst,
    const float* __restrict__ mean, const float* __restrict__ rstd,
    const float* __restrict__ gg, const float* __restrict__ bb, int C, long total4)
{
    const float4* s4 = reinterpret_cast<const float4*>(src);
    float4* d4 = reinterpret_cast<float4*>(dst);
    long stride = (long)gridDim.x * blockDim.x;
    for (long i = (long)blockIdx.x * blockDim.x + threadIdx.x; i < total4; i += stride) {
        int c = (int)((i >> 8) % C);
        float sc = rstd[c] * gg[c];
        float shf = bb[c] - mean[c] * sc;
        float4 v = s4[i];
        v.x = gelu_exact(v.x * sc + shf); v.y = gelu_exact(v.y * sc + shf);
        v.z = gelu_exact(v.z * sc + shf); v.w = gelu_exact(v.w * sc + shf);
        d4[i] = v;
    }
}

// ---------------- launch ----------------
extern "C" void kernel_launch(void* const* d_in, const int* in_sizes, int n_in,
                              void* d_out, int out_size)
{
    const float* x       = (const float*)d_in[0];
    const float* w_qkv   = (const float*)d_in[1];
    const float* gqkv    = (const float*)d_in[2];
    const float* bqkv    = (const float*)d_in[3];
    const float* w_merge = (const float*)d_in[4];
    const float* gmerge  = (const float*)d_in[5];
    const float* bmerge  = (const float*)d_in[6];
    const float* w_fc1   = (const float*)d_in[7];
    const float* gfc1    = (const float*)d_in[8];
    const float* bfc1    = (const float*)d_in[9];
    const float* w_fc2   = (const float*)d_in[10];
    const float* gfc2    = (const float*)d_in[11];
    const float* bfc2    = (const float*)d_in[12];
    float* out = (float*)d_out;

    float *yb, *attb, *o2b, *x2b, *h1b, *tmpb, *meanb, *rstdb;
    cudaGetSymbolAddress((void**)&yb,    g_y);
    cudaGetSymbolAddress((void**)&attb,  g_att);
    cudaGetSymbolAddress((void**)&o2b,   g_o2);
    cudaGetSymbolAddress((void**)&x2b,   g_x2);
    cudaGetSymbolAddress((void**)&h1b,   g_h1);
    cudaGetSymbolAddress((void**)&tmpb,  g_tmp);
    cudaGetSymbolAddress((void**)&meanb, g_mean);
    cudaGetSymbolAddress((void**)&rstdb, g_rstd);

    const float scale = 0.17677669529663687f; // 32^-0.5

    // 1) qkv conv1x1: y[b,1536,1024] = w_qkv(1536x384) @ x_b(384x1024)
    mm_tf32<0,0,0,0><<<dim3(Nn/128, QKV_C/128, Bb), 256>>>(
        w_qkv, x, yb, QKV_C, Nn, Cc, Cc, Nn, (long)Cc*Nn, (long)QKV_C*Nn, 1.f);
    // 2) BN(qkv)
    bn_stats<<<QKV_C, 256>>>(yb, meanb, rstdb, QKV_C);
    bn_apply_inplace<<<2048, 256>>>(yb, meanb, rstdb, gqkv, bqkv, QKV_C, (long)Bb*QKV_C*Nn/4);
    // 3) att = softmax(scale * q^T k)
    mm_tf32<1,0,1,1><<<dim3(Nn/128, Nn/128, Bb*HEADS), 256>>>(
        yb, yb, attb, Nn, Nn, KD, Nn, Nn, 0, 0, scale);
    softmax_rows<<<Bb*HEADS*Nn, 256>>>(attb);
    // 4) o2 = gelu(V @ att^T)
    mm_tf32<0,1,2,2><<<dim3(Nn/128, VD/128, Bb*HEADS), 256>>>(
        yb, attb, o2b, VD, Nn, Nn, Nn, Nn, 0, 0, 1.f);
    // 5) merge conv + BN + residual -> x2
    mm_tf32<0,0,0,0><<<dim3(Nn/128, Cc/128, Bb), 256>>>(
        w_merge, o2b, tmpb, Cc, Nn, HEADS*VD, HEADS*VD, Nn, (long)HEADS*VD*Nn, (long)Cc*Nn, 1.f);
    bn_stats<<<Cc, 256>>>(tmpb, meanb, rstdb, Cc);
    bn_apply_residual<<<1024, 256>>>(tmpb, x, x2b, meanb, rstdb, gmerge, bmerge, Cc, (long)Bb*Cc*Nn/4);
    // 6) fc1 + BN + gelu -> h1
    mm_tf32<0,0,0,0><<<dim3(Nn/128, FC1_C/128, Bb), 256>>>(
        w_fc1, x2b, tmpb, FC1_C, Nn, Cc, Cc, Nn, (long)Cc*Nn, (long)FC1_C*Nn, 1.f);
    bn_stats<<<FC1_C, 256>>>(tmpb, meanb, rstdb, FC1_C);
    bn_apply_gelu<<<1536, 256>>>(tmpb, h1b, meanb, rstdb, gfc1, bfc1, FC1_C, (long)Bb*FC1_C*Nn/4);
    // 7) fc2 + BN + residual -> out
    mm_tf32<0,0,0,0><<<dim3(Nn/128, Cc/128, Bb), 256>>>(
        w_fc2, h1b, tmpb, Cc, Nn, FC1_C, FC1_C, Nn, (long)FC1_C*Nn, (long)Cc*Nn, 1.f);
    bn_stats<<<Cc, 256>>>(tmpb, meanb, rstdb, Cc);
    bn_apply_residual<<<1024, 256>>>(tmpb, x2b, out, meanb, rstdb, gfc2, bfc2, Cc, (long)Bb*Cc*Nn/4);
}

// round 3
// speedup vs baseline: 2.5270x; 1.0349x over previous
#include <cuda_runtime.h>
#include <math.h>
#include <stdint.h>

#define Bb 8
#define Cc 384
#define Nn 1024
#define HEADS 8
#define KD 32
#define VD 128
#define QKV_C 1536
#define FC1_C 768
#define EPS 1e-5f

// ---------------- scratch (static device globals; no allocation) ----------------
__device__ float g_y[(long)Bb*QKV_C*Nn];        // qkv post-norm       (50 MB)
__device__ float g_vt[(long)Bb*HEADS*Nn*VD];    // V transposed [z][n][dv] (33 MB)
__device__ float g_o2t[(long)Bb*Nn*HEADS*VD];   // gelu(attn out) [b][n][ch] (33 MB)
__device__ float g_x2[(long)Bb*Cc*Nn];          // x + merge branch
__device__ float g_h1[(long)Bb*FC1_C*Nn];       // gelu(fc1 norm)
__device__ float g_tmp[(long)Bb*FC1_C*Nn];      // gemm outputs pre-norm
__device__ float g_mean[QKV_C];
__device__ float g_rstd[QKV_C];

__device__ __forceinline__ float warpSum(float v){
    #pragma unroll
    for (int o=16;o;o>>=1) v += __shfl_xor_sync(0xffffffffu, v, o);
    return v;
}
__device__ __forceinline__ float gelu_exact(float x){
    return 0.5f * x * (1.0f + erff(x * 0.7071067811865476f));
}
// round fp32 -> tf32 (RNA)
__device__ __forceinline__ float to_tf32(float x){
    uint32_t u;
    asm("cvt.rna.tf32.f32 %0, %1;" : "=r"(u) : "f"(x));
    return __uint_as_float(u);
}
__device__ __forceinline__ void mma_tf32(float c[4],
    uint32_t a0, uint32_t a1, uint32_t a2, uint32_t a3, uint32_t b0, uint32_t b1)
{
    asm volatile("mma.sync.aligned.m16n8k8.row.col.f32.tf32.tf32.f32 "
        "{%0,%1,%2,%3}, {%4,%5,%6,%7}, {%8,%9}, {%0,%1,%2,%3};"
        : "+f"(c[0]), "+f"(c[1]), "+f"(c[2]), "+f"(c[3])
        : "r"(a0), "r"(a1), "r"(a2), "r"(a3), "r"(b0), "r"(b1));
}

// =====================================================================
// Unified tf32 tensor-core GEMM (unchanged from round 2, passing).
// =====================================================================
#define SMS 136

template<int AMODE,int BMODE,int ZMODE,int EPI>
__global__ __launch_bounds__(256,2) void mm_tf32(
    const float* __restrict__ A, const float* __restrict__ B, float* __restrict__ C,
    int M, int N, int K, int lda, int ldb,
    long strideB, long strideC, float alpha)
{
    __shared__ __align__(16) float As[2][16][SMS];
    __shared__ __align__(16) float Bs[2][16][SMS];

    const int z = blockIdx.z;
    long aOff, bOff, cOff;
    aOff = 0; bOff = (long)z * strideB; cOff = (long)z * strideC;
    const float* Ab = A + aOff;
    const float* Bc = B + bOff;
    float* Cz = C + cOff;

    const int bm = blockIdx.y * 128, bn = blockIdx.x * 128;
    const int tid = threadIdx.x;
    const int w = tid >> 5, l = tid & 31;
    const int wm = (w >> 1) * 32, wn = (w & 1) * 64;
    const int r = l >> 2, qc = l & 3;

    float acc[2][8][4];
    #pragma unroll
    for (int i = 0; i < 2; i++)
        #pragma unroll
        for (int j = 0; j < 8; j++)
            #pragma unroll
            for (int k = 0; k < 4; k++) acc[i][j][k] = 0.f;

    float4 ra[2], rb[2];

    auto gload = [&](int k0){
        #pragma unroll
        for (int j = 0; j < 2; j++){
            int i = tid + j*256;
            if (AMODE == 0) { int row = i >> 2, kq = (i & 3) * 4;
                ra[j] = *reinterpret_cast<const float4*>(&Ab[(long)(bm+row)*lda + k0+kq]); }
            else            { int kk = i >> 5, mq = (i & 31) * 4;
                ra[j] = *reinterpret_cast<const float4*>(&Ab[(long)(k0+kk)*lda + bm+mq]); }
        }
        #pragma unroll
        for (int j = 0; j < 2; j++){
            int i = tid + j*256;
            if (BMODE == 0) { int kk = i >> 5, nq = (i & 31) * 4;
                rb[j] = *reinterpret_cast<const float4*>(&Bc[(long)(k0+kk)*ldb + bn+nq]); }
            else            { int row = i >> 2, kq = (i & 3) * 4;
                rb[j] = *reinterpret_cast<const float4*>(&Bc[(long)(bn+row)*ldb + k0+kq]); }
        }
    };

    auto sstore = [&](int buf){
        #pragma unroll
        for (int j = 0; j < 2; j++){
            int i = tid + j*256;
            if (AMODE == 0) { int row = i >> 2, kq = (i & 3) * 4;
                As[buf][kq+0][row] = to_tf32(ra[j].x);
                As[buf][kq+1][row] = to_tf32(ra[j].y);
                As[buf][kq+2][row] = to_tf32(ra[j].z);
                As[buf][kq+3][row] = to_tf32(ra[j].w); }
            else            { int kk = i >> 5, mq = (i & 31) * 4;
                As[buf][kk][mq+0] = to_tf32(ra[j].x);
                As[buf][kk][mq+1] = to_tf32(ra[j].y);
                As[buf][kk][mq+2] = to_tf32(ra[j].z);
                As[buf][kk][mq+3] = to_tf32(ra[j].w); }
        }
        #pragma unroll
        for (int j = 0; j < 2; j++){
            int i = tid + j*256;
            if (BMODE == 0) { int kk = i >> 5, nq = (i & 31) * 4;
                Bs[buf][kk][nq+0] = to_tf32(rb[j].x);
                Bs[buf][kk][nq+1] = to_tf32(rb[j].y);
                Bs[buf][kk][nq+2] = to_tf32(rb[j].z);
                Bs[buf][kk][nq+3] = to_tf32(rb[j].w); }
            else            { int row = i >> 2, kq = (i & 3) * 4;
                Bs[buf][kq+0][row] = to_tf32(rb[j].x);
                Bs[buf][kq+1][row] = to_tf32(rb[j].y);
                Bs[buf][kq+2][row] = to_tf32(rb[j].z);
                Bs[buf][kq+3][row] = to_tf32(rb[j].w); }
        }
    };

    auto compute = [&](int buf){
        #pragma unroll
        for (int ks = 0; ks < 16; ks += 8){
            uint32_t af[2][4], bf[8][2];
            #pragma unroll
            for (int im = 0; im < 2; im++){
                af[im][0] = __float_as_uint(As[buf][ks+qc  ][wm+im*16+r  ]);
                af[im][1] = __float_as_uint(As[buf][ks+qc  ][wm+im*16+r+8]);
                af[im][2] = __float_as_uint(As[buf][ks+qc+4][wm+im*16+r  ]);
                af[im][3] = __float_as_uint(As[buf][ks+qc+4][wm+im*16+r+8]);
            }
            #pragma unroll
            for (int jn = 0; jn < 8; jn++){
                bf[jn][0] = __float_as_uint(Bs[buf][ks+qc  ][wn+jn*8+r]);
                bf[jn][1] = __float_as_uint(Bs[buf][ks+qc+4][wn+jn*8+r]);
            }
            #pragma unroll
            for (int im = 0; im < 2; im++)
                #pragma unroll
                for (int jn = 0; jn < 8; jn++)
                    mma_tf32(acc[im][jn], af[im][0], af[im][1], af[im][2], af[im][3],
                             bf[jn][0], bf[jn][1]);
        }
    };

    gload(0); sstore(0); __syncthreads();
    int buf = 0;
    for (int k0 = 0; k0 < K; k0 += 16){
        bool more = (k0 + 16) < K;
        if (more) gload(k0 + 16);
        compute(buf);
        if (more) { sstore(buf ^ 1); buf ^= 1; }
        __syncthreads();
    }

    #pragma unroll
    for (int im = 0; im < 2; im++){
        #pragma unroll
        for (int jn = 0; jn < 8; jn++){
            float v0 = acc[im][jn][0], v1 = acc[im][jn][1];
            float v2 = acc[im][jn][2], v3 = acc[im][jn][3];
            if (EPI == 1) { v0 *= alpha; v1 *= alpha; v2 *= alpha; v3 *= alpha; }
            if (EPI == 2) { v0 = gelu_exact(v0); v1 = gelu_exact(v1);
                            v2 = gelu_exact(v2); v3 = gelu_exact(v3); }
            int row = bm + wm + im*16 + r;
            int col = bn + wn + jn*8 + 2*qc;
            *reinterpret_cast<float2*>(&Cz[(long)row * N + col])     = make_float2(v0, v1);
            *reinterpret_cast<float2*>(&Cz[(long)(row+8) * N + col]) = make_float2(v2, v3);
        }
    }
}

// =====================================================================
// V transpose: vt[z][n][dv] = tf32( y[b][h*192+64+dv][n] )
// =====================================================================
__global__ __launch_bounds__(256) void transpose_v(const float* __restrict__ y,
                                                   float* __restrict__ vt)
{
    __shared__ float t[32][33];
    const int z = blockIdx.z, b = z >> 3, h = z & 7;
    const float* V = y + ((long)b * QKV_C + h * 192 + 64) * Nn;
    const int n0 = blockIdx.x * 32, d0 = blockIdx.y * 32;
    const int tx = threadIdx.x, ty = threadIdx.y;  // 32 x 8
    #pragma unroll
    for (int j = 0; j < 4; j++)
        t[ty + j*8][tx] = V[(long)(d0 + ty + j*8) * Nn + n0 + tx];
    __syncthreads();
    float* dst = vt + (long)z * Nn * VD;
    #pragma unroll
    for (int j = 0; j < 4; j++)
        dst[(long)(n0 + ty + j*8) * VD + d0 + tx] = to_tf32(t[tx][ty + j*8]);
}

// =====================================================================
// Flash attention: per (b,h), 128-query blocks, 64-key tiles, online softmax.
// o2t[b][n][h*128+dv] = gelu( sum_k softmax(scale*Q^T K)[n,k] * V[dv,k] )
// 8 warps, each owns 16 query rows (full width). tf32 mma for S and PV.
// =====================================================================
#define FSM_Q 0                    // Qs [32][136]
#define FSM_K (32*136)             // Ks [32][72]
#define FSM_V (32*136 + 32*72)     // Vs [64][136]
#define FSM_P (32*136 + 32*72 + 64*136) // Ps [64][136]
#define FSM_TOTAL ((32*136 + 32*72 + 64*136 + 64*136) * 4)

__global__ __launch_bounds__(256) void flash_att(
    const float* __restrict__ y, const float* __restrict__ vt,
    float* __restrict__ o2t, float scale)
{
    extern __shared__ float sm[];
    float* Qs = sm + FSM_Q;
    float* Ks = sm + FSM_K;
    float* Vs = sm + FSM_V;
    float* Ps = sm + FSM_P;

    const int z = blockIdx.y, b = z >> 3, h = z & 7;
    const float* Q   = y + ((long)b * QKV_C + h * 192) * Nn;  // [32][1024]
    const float* Kg  = Q + 32 * Nn;                            // [32][1024]
    const float* Vtz = vt + (long)z * Nn * VD;                 // [1024][128]
    const int qt = blockIdx.x * 128;
    const int tid = threadIdx.x, w = tid >> 5, l = tid & 31;
    const int r = l >> 2, qc = l & 3;
    const int wq = w * 16;

    // Q tile [32 d][128 q] -> tf32
    for (int i = tid; i < 32*32; i += 256) {
        int d = i >> 5, c = (i & 31) * 4;
        float4 v = *reinterpret_cast<const float4*>(&Q[(long)d * Nn + qt + c]);
        Qs[d*136 + c+0] = to_tf32(v.x);
        Qs[d*136 + c+1] = to_tf32(v.y);
        Qs[d*136 + c+2] = to_tf32(v.z);
        Qs[d*136 + c+3] = to_tf32(v.w);
    }

    float oacc[16][4];
    #pragma unroll
    for (int j = 0; j < 16; j++)
        oacc[j][0] = oacc[j][1] = oacc[j][2] = oacc[j][3] = 0.f;
    float m0 = -1e30f, m1 = -1e30f, l0 = 0.f, l1 = 0.f;

    for (int kt = 0; kt < Nn; kt += 64) {
        // K tile [32 d][64 keys] -> tf32
        for (int i = tid; i < 32*16; i += 256) {
            int d = i >> 4, c = (i & 15) * 4;
            float4 v = *reinterpret_cast<const float4*>(&Kg[(long)d * Nn + kt + c]);
            Ks[d*72 + c+0] = to_tf32(v.x);
            Ks[d*72 + c+1] = to_tf32(v.y);
            Ks[d*72 + c+2] = to_tf32(v.z);
            Ks[d*72 + c+3] = to_tf32(v.w);
        }
        // V tile [64 k][128 dv] (already tf32)
        for (int i = tid; i < 64*32; i += 256) {
            int kk = i >> 5, c = (i & 31) * 4;
            *reinterpret_cast<float4*>(&Vs[kk*136 + c]) =
                *reinterpret_cast<const float4*>(&Vtz[(long)(kt + kk) * VD + c]);
        }
        __syncthreads();

        // S = scale * Q^T K  (warp: 16 q rows x 64 keys)
        float sacc[8][4];
        #pragma unroll
        for (int j = 0; j < 8; j++)
            sacc[j][0] = sacc[j][1] = sacc[j][2] = sacc[j][3] = 0.f;
        #pragma unroll
        for (int ks = 0; ks < 32; ks += 8) {
            uint32_t a0 = __float_as_uint(Qs[(ks+qc  )*136 + wq + r    ]);
            uint32_t a1 = __float_as_uint(Qs[(ks+qc  )*136 + wq + r + 8]);
            uint32_t a2 = __float_as_uint(Qs[(ks+qc+4)*136 + wq + r    ]);
            uint32_t a3 = __float_as_uint(Qs[(ks+qc+4)*136 + wq + r + 8]);
            #pragma unroll
            for (int jn = 0; jn < 8; jn++) {
                uint32_t b0 = __float_as_uint(Ks[(ks+qc  )*72 + jn*8 + r]);
                uint32_t b1 = __float_as_uint(Ks[(ks+qc+4)*72 + jn*8 + r]);
                mma_tf32(sacc[jn], a0, a1, a2, a3, b0, b1);
            }
        }

        // online softmax (rows r and r+8 of this warp's 16)
        float mx0 = -1e30f, mx1 = -1e30f;
        #pragma unroll
        for (int jn = 0; jn < 8; jn++) {
            sacc[jn][0] *= scale; sacc[jn][1] *= scale;
            sacc[jn][2] *= scale; sacc[jn][3] *= scale;
            mx0 = fmaxf(mx0, fmaxf(sacc[jn][0], sacc[jn][1]));
            mx1 = fmaxf(mx1, fmaxf(sacc[jn][2], sacc[jn][3]));
        }
        mx0 = fmaxf(mx0, __shfl_xor_sync(0xffffffffu, mx0, 1));
        mx0 = fmaxf(mx0, __shfl_xor_sync(0xffffffffu, mx0, 2));
        mx1 = fmaxf(mx1, __shfl_xor_sync(0xffffffffu, mx1, 1));
        mx1 = fmaxf(mx1, __shfl_xor_sync(0xffffffffu, mx1, 2));
        float nm0 = fmaxf(m0, mx0), nm1 = fmaxf(m1, mx1);
        float corr0 = __expf(m0 - nm0), corr1 = __expf(m1 - nm1);
        float rs0 = 0.f, rs1 = 0.f;
        #pragma unroll
        for (int jn = 0; jn < 8; jn++) {
            sacc[jn][0] = __expf(sacc[jn][0] - nm0);
            sacc[jn][1] = __expf(sacc[jn][1] - nm0);
            sacc[jn][2] = __expf(sacc[jn][2] - nm1);
            sacc[jn][3] = __expf(sacc[jn][3] - nm1);
            rs0 += sacc[jn][0] + sacc[jn][1];
            rs1 += sacc[jn][2] + sacc[jn][3];
        }
        rs0 += __shfl_xor_sync(0xffffffffu, rs0, 1);
        rs0 += __shfl_xor_sync(0xffffffffu, rs0, 2);
        rs1 += __shfl_xor_sync(0xffffffffu, rs1, 1);
        rs1 += __shfl_xor_sync(0xffffffffu, rs1, 2);
        l0 = l0 * corr0 + rs0;  m0 = nm0;
        l1 = l1 * corr1 + rs1;  m1 = nm1;
        #pragma unroll
        for (int j = 0; j < 16; j++) {
            oacc[j][0] *= corr0; oacc[j][1] *= corr0;
            oacc[j][2] *= corr1; oacc[j][3] *= corr1;
        }

        // P -> smem  Ps[k][q] (warp-private q columns)
        #pragma unroll
        for (int jn = 0; jn < 8; jn++) {
            int col = jn*8 + 2*qc;
            Ps[(col  )*136 + wq + r    ] = to_tf32(sacc[jn][0]);
            Ps[(col+1)*136 + wq + r    ] = to_tf32(sacc[jn][1]);
            Ps[(col  )*136 + wq + r + 8] = to_tf32(sacc[jn][2]);
            Ps[(col+1)*136 + wq + r + 8] = to_tf32(sacc[jn][3]);
        }
        __syncwarp();

        // O += P @ V^T  (warp: 16 q rows x 128 dv)
        #pragma unroll
        for (int ks = 0; ks < 64; ks += 8) {
            uint32_t a0 = __float_as_uint(Ps[(ks+qc  )*136 + wq + r    ]);
            uint32_t a1 = __float_as_uint(Ps[(ks+qc  )*136 + wq + r + 8]);
            uint32_t a2 = __float_as_uint(Ps[(ks+qc+4)*136 + wq + r    ]);
            uint32_t a3 = __float_as_uint(Ps[(ks+qc+4)*136 + wq + r + 8]);
            #pragma unroll
            for (int jn = 0; jn < 16; jn++) {
                uint32_t b0 = __float_as_uint(Vs[(ks+qc  )*136 + jn*8 + r]);
                uint32_t b1 = __float_as_uint(Vs[(ks+qc+4)*136 + jn*8 + r]);
                mma_tf32(oacc[jn], a0, a1, a2, a3, b0, b1);
            }
        }
        __syncthreads();
    }

    // epilogue: normalize, gelu, write o2t[b][n][h*128+dv]
    float inv0 = 1.f / l0, inv1 = 1.f / l1;
    #pragma unroll
    for (int jn = 0; jn < 16; jn++) {
        int ch = h * VD + jn*8 + 2*qc;
        float v0 = gelu_exact(oacc[jn][0] * inv0);
        float v1 = gelu_exact(oacc[jn][1] * inv0);
        float v2 = gelu_exact(oacc[jn][2] * inv1);
        float v3 = gelu_exact(oacc[jn][3] * inv1);
        long base = ((long)b * Nn + qt + wq + r) * (long)(HEADS*VD) + ch;
        *reinterpret_cast<float2*>(&o2t[base]) = make_float2(v0, v1);
        *reinterpret_cast<float2*>(&o2t[base + 8L*(HEADS*VD)]) = make_float2(v2, v3);
    }
}

// ---------------- BN stats: one block per channel, reduce over B*N = 8192 --------
__global__ __launch_bounds__(256) void bn_stats(const float* __restrict__ y, float* __restrict__ mean,
                                                float* __restrict__ rstd, int C)
{
    const int c = blockIdx.x;
    float s = 0.f, s2 = 0.f;
    for (int i = threadIdx.x; i < Bb * Nn / 4; i += 256) {
        int b = i >> 8, n4 = i & 255;
        float4 v = *reinterpret_cast<const float4*>(&y[((long)b * C + c) * Nn + n4 * 4]);
        s  += v.x + v.y + v.z + v.w;
        s2 += v.x*v.x + v.y*v.y + v.z*v.z + v.w*v.w;
    }
    __shared__ float ss[8], ss2[8];
    s = warpSum(s); s2 = warpSum(s2);
    int w = threadIdx.x >> 5;
    if ((threadIdx.x & 31) == 0) { ss[w] = s; ss2[w] = s2; }
    __syncthreads();
    if (threadIdx.x == 0) {
        float ts = 0.f, ts2 = 0.f;
        #pragma unroll
        for (int i = 0; i < 8; i++) { ts += ss[i]; ts2 += ss2[i]; }
        float m = ts / (float)(Bb * Nn);
        float var = ts2 / (float)(Bb * Nn) - m * m;
        mean[c] = m;
        rstd[c] = rsqrtf(var + EPS);
    }
}

// ---------------- BN apply variants (float4) ----------------
__global__ __launch_bounds__(256) void bn_apply_inplace(float* __restrict__ y,
    const float* __restrict__ mean, const float* __restrict__ rstd,
    const float* __restrict__ gg, const float* __restrict__ bb, int C, long total4)
{
    float4* p = reinterpret_cast<float4*>(y);
    long stride = (long)gridDim.x * blockDim.x;
    for (long i = (long)blockIdx.x * blockDim.x + threadIdx.x; i < total4; i += stride) {
        int c = (int)((i >> 8) % C);
        float sc = rstd[c] * gg[c];
        float sh = bb[c] - mean[c] * sc;
        float4 v = p[i];
        v.x = v.x * sc + sh; v.y = v.y * sc + sh; v.z = v.z * sc + sh; v.w = v.w * sc + sh;
        p[i] = v;
    }
}

__global__ __launch_bounds__(256) void bn_apply_residual(const float* __restrict__ src, const float* __restrict__ res,
    float* __restrict__ dst, const float* __restrict__ mean, const float* __restrict__ rstd,
    const float* __restrict__ gg, const float* __restrict__ bb, int C, long total4)
{
    const float4* s4 = reinterpret_cast<const float4*>(src);
    const float4* r4 = reinterpret_cast<const float4*>(res);
    float4* d4 = reinterpret_cast<float4*>(dst);
    long stride = (long)gridDim.x * blockDim.x;
    for (long i = (long)blockIdx.x * blockDim.x + threadIdx.x; i < total4; i += stride) {
        int c = (int)((i >> 8) % C);
        float sc = rstd[c] * gg[c];
        float shf = bb[c] - mean[c] * sc;
        float4 v = s4[i]; float4 rr = r4[i];
        v.x = rr.x + v.x * sc + shf; v.y = rr.y + v.y * sc + shf;
        v.z = rr.z + v.z * sc + shf; v.w = rr.w + v.w * sc + shf;
        d4[i] = v;
    }
}

__global__ __launch_bounds__(256) void bn_apply_gelu(const float* __restrict__ src, float* __restrict__ dst,
    const float* __restrict__ mean, const float* __restrict__ rstd,
    const float* __restrict__ gg, const float* __restrict__ bb, int C, long total4)
{
    const float4* s4 = reinterpret_cast<const float4*>(src);
    float4* d4 = reinterpret_cast<float4*>(dst);
    long stride = (long)gridDim.x * blockDim.x;
    for (long i = (long)blockIdx.x * blockDim.x + threadIdx.x; i < total4; i += stride) {
        int c = (int)((i >> 8) % C);
        float sc = rstd[c] * gg[c];
        float shf = bb[c] - mean[c] * sc;
        float4 v = s4[i];
        v.x = gelu_exact(v.x * sc + shf); v.y = gelu_exact(v.y * sc + shf);
        v.z = gelu_exact(v.z * sc + shf); v.w = gelu_exact(v.w * sc + shf);
        d4[i] = v;
    }
}

// ---------------- launch ----------------
extern "C" void kernel_launch(void* const* d_in, const int* in_sizes, int n_in,
                              void* d_out, int out_size)
{
    const float* x       = (const float*)d_in[0];
    const float* w_qkv   = (const float*)d_in[1];
    const float* gqkv    = (const float*)d_in[2];
    const float* bqkv    = (const float*)d_in[3];
    const float* w_merge = (const float*)d_in[4];
    const float* gmerge  = (const float*)d_in[5];
    const float* bmerge  = (const float*)d_in[6];
    const float* w_fc1   = (const float*)d_in[7];
    const float* gfc1    = (const float*)d_in[8];
    const float* bfc1    = (const float*)d_in[9];
    const float* w_fc2   = (const float*)d_in[10];
    const float* gfc2    = (const float*)d_in[11];
    const float* bfc2    = (const float*)d_in[12];
    float* out = (float*)d_out;

    float *yb, *vtb, *o2tb, *x2b, *h1b, *tmpb, *meanb, *rstdb;
    cudaGetSymbolAddress((void**)&yb,    g_y);
    cudaGetSymbolAddress((void**)&vtb,   g_vt);
    cudaGetSymbolAddress((void**)&o2tb,  g_o2t);
    cudaGetSymbolAddress((void**)&x2b,   g_x2);
    cudaGetSymbolAddress((void**)&h1b,   g_h1);
    cudaGetSymbolAddress((void**)&tmpb,  g_tmp);
    cudaGetSymbolAddress((void**)&meanb, g_mean);
    cudaGetSymbolAddress((void**)&rstdb, g_rstd);

    static bool attr_done = false;
    if (!attr_done) {
        cudaFuncSetAttribute(flash_att, cudaFuncAttributeMaxDynamicSharedMemorySize, FSM_TOTAL);
        attr_done = true;
    }

    const float scale = 0.17677669529663687f; // 32^-0.5

    // 1) qkv conv1x1: y[b,1536,1024] = w_qkv(1536x384) @ x_b(384x1024)
    mm_tf32<0,0,0,0><<<dim3(Nn/128, QKV_C/128, Bb), 256>>>(
        w_qkv, x, yb, QKV_C, Nn, Cc, Cc, Nn, (long)Cc*Nn, (long)QKV_C*Nn, 1.f);
    // 2) BN(qkv)
    bn_stats<<<QKV_C, 256>>>(yb, meanb, rstdb, QKV_C);
    bn_apply_inplace<<<2048, 256>>>(yb, meanb, rstdb, gqkv, bqkv, QKV_C, (long)Bb*QKV_C*Nn/4);
    // 3) V transpose (tf32)
    transpose_v<<<dim3(Nn/32, VD/32, Bb*HEADS), dim3(32,8)>>>(yb, vtb);
    // 4) flash attention + gelu -> o2t[b][n][ch]
    flash_att<<<dim3(Nn/128, Bb*HEADS), 256, FSM_TOTAL>>>(yb, vtb, o2tb, scale);
    // 5) merge conv + BN + residual -> x2   (B = o2t via BMODE1)
    mm_tf32<0,1,0,0><<<dim3(Nn/128, Cc/128, Bb), 256>>>(
        w_merge, o2tb, tmpb, Cc, Nn, HEADS*VD, HEADS*VD, HEADS*VD,
        (long)Nn*HEADS*VD, (long)Cc*Nn, 1.f);
    bn_stats<<<Cc, 256>>>(tmpb, meanb, rstdb, Cc);
    bn_apply_residual<<<1024, 256>>>(tmpb, x, x2b, meanb, rstdb, gmerge, bmerge, Cc, (long)Bb*Cc*Nn/4);
    // 6) fc1 + BN + gelu -> h1
    mm_tf32<0,0,0,0><<<dim3(Nn/128, FC1_C/128, Bb), 256>>>(
        w_fc1, x2b, tmpb, FC1_C, Nn, Cc, Cc, Nn, (long)Cc*Nn, (long)FC1_C*Nn, 1.f);
    bn_stats<<<FC1_C, 256>>>(tmpb, meanb, rstdb, FC1_C);
    bn_apply_gelu<<<1536, 256>>>(tmpb, h1b, meanb, rstdb, gfc1, bfc1, FC1_C, (long)Bb*FC1_C*Nn/4);
    // 7) fc2 + BN + residual -> out
    mm_tf32<0,0,0,0><<<dim3(Nn/128, Cc/128, Bb), 256>>>(
        w_fc2, h1b, tmpb, Cc, Nn, FC1_C, FC1_C, Nn, (long)FC1_C*Nn, (long)Cc*Nn, 1.f);
    bn_stats<<<Cc, 256>>>(tmpb, meanb, rstdb, Cc);
    bn_apply_residual<<<1024, 256>>>(tmpb, x2b, out, meanb, rstdb, gfc2, bfc2, Cc, (long)Bb*Cc*Nn/4);
}